// round 11
// baseline (speedup 1.0000x reference)
#include <cuda_runtime.h>
#include <cuda_bf16.h>
#include <cstdint>
#include <math.h>

#define B_     2
#define L_     2048
#define HID_   4096
#define NHEAD_ 32
#define NKV_   8
#define HDIM_  128
#define MROWS  (B_*L_)          // 4096
#define KVW    (2*NKV_*HDIM_)   // 2048
#define VW     (NKV_*HDIM_)     // 1024

// ------------------------- device scratch (no allocs) -----------------------
__device__ __align__(256) __nv_bfloat16 g_qin_h [(size_t)MROWS * HID_];
__device__ __align__(256) __nv_bfloat16 g_qin_l [(size_t)MROWS * HID_];
__device__ __align__(256) __nv_bfloat16 g_kvin_h[(size_t)MROWS * HID_];
__device__ __align__(256) __nv_bfloat16 g_kvin_l[(size_t)MROWS * HID_];
__device__ __align__(256) __nv_bfloat16 g_att_h [(size_t)MROWS * HID_];
__device__ __align__(256) __nv_bfloat16 g_att_l [(size_t)MROWS * HID_];
__device__ __align__(256) __nv_bfloat16 g_wqt_h [(size_t)HID_ * HID_];
__device__ __align__(256) __nv_bfloat16 g_wqt_l [(size_t)HID_ * HID_];
__device__ __align__(256) __nv_bfloat16 g_wkvt_h[(size_t)KVW  * HID_];
__device__ __align__(256) __nv_bfloat16 g_wkvt_l[(size_t)KVW  * HID_];
__device__ __align__(256) __nv_bfloat16 g_wot_h [(size_t)HID_ * HID_];
__device__ __align__(256) __nv_bfloat16 g_wot_l [(size_t)HID_ * HID_];
// attention operands (bf16 hi/lo)
__device__ __align__(256) __nv_bfloat16 g_aqh[(size_t)MROWS * HID_];  // scaled Q
__device__ __align__(256) __nv_bfloat16 g_aql[(size_t)MROWS * HID_];
__device__ __align__(256) __nv_bfloat16 g_kh [(size_t)B_*NKV_*L_*HDIM_]; // [b,kvh,l,d]
__device__ __align__(256) __nv_bfloat16 g_kl [(size_t)B_*NKV_*L_*HDIM_];
__device__ __align__(256) __nv_bfloat16 g_vth[(size_t)B_*NKV_*HDIM_*L_]; // [b,kvh,d,l]
__device__ __align__(256) __nv_bfloat16 g_vtl[(size_t)B_*NKV_*HDIM_*L_];

// ------------------------------ PTX helpers ---------------------------------
__device__ __forceinline__ uint32_t smem_u32(const void* p) {
    uint32_t a;
    asm("{ .reg .u64 t; cvta.to.shared.u64 t, %1; cvt.u32.u64 %0, t; }"
        : "=r"(a) : "l"(p));
    return a;
}

__device__ __forceinline__ void ldsm4(uint32_t* r, uint32_t addr) {
    asm volatile("ldmatrix.sync.aligned.m8n8.x4.shared.b16 {%0,%1,%2,%3}, [%4];"
                 : "=r"(r[0]), "=r"(r[1]), "=r"(r[2]), "=r"(r[3]) : "r"(addr));
}

__device__ __forceinline__ void mma16816(float* d, const uint32_t* a,
                                         const uint32_t* b) {
    asm volatile(
        "mma.sync.aligned.m16n8k16.row.col.f32.bf16.bf16.f32 "
        "{%0,%1,%2,%3}, {%4,%5,%6,%7}, {%8,%9}, {%0,%1,%2,%3};"
        : "+f"(d[0]), "+f"(d[1]), "+f"(d[2]), "+f"(d[3])
        : "r"(a[0]), "r"(a[1]), "r"(a[2]), "r"(a[3]), "r"(b[0]), "r"(b[1]));
}

#define CP16(saddr, gaddr) \
    asm volatile("cp.async.cg.shared.global [%0], [%1], 16;" \
                 :: "r"(saddr), "l"(gaddr) : "memory")
#define CP_COMMIT()  asm volatile("cp.async.commit_group;" ::: "memory")
#define CP_WAIT0()   asm volatile("cp.async.wait_group 0;" ::: "memory")

__device__ __forceinline__ unsigned short f2bf_bits(float x) {
    __nv_bfloat16 h = __float2bfloat16(x);
    return *(unsigned short*)&h;
}
__device__ __forceinline__ float bf_bits2f(unsigned short b) {
    __nv_bfloat16 h = *(__nv_bfloat16*)&b;
    return __bfloat162float(h);
}
__device__ __forceinline__ uint32_t pack_hi(float a, float b) {
    return (uint32_t)f2bf_bits(a) | ((uint32_t)f2bf_bits(b) << 16);
}
__device__ __forceinline__ uint32_t pack_lo(float a, float b) {
    unsigned short ha = f2bf_bits(a), hb = f2bf_bits(b);
    return (uint32_t)f2bf_bits(a - bf_bits2f(ha))
         | ((uint32_t)f2bf_bits(b - bf_bits2f(hb)) << 16);
}
__device__ __forceinline__ void store_bf_pair(__nv_bfloat16* Ph, __nv_bfloat16* Pl,
                                              size_t idx, float v) {
    unsigned short h = f2bf_bits(v);
    unsigned short l = f2bf_bits(v - bf_bits2f(h));
    Ph[idx] = *(__nv_bfloat16*)&h;
    Pl[idx] = *(__nv_bfloat16*)&l;
}

// ---------------------------- conversion kernels ----------------------------
__global__ __launch_bounds__(256) void split_k(const float* __restrict__ in,
                                               __nv_bfloat16* __restrict__ hi,
                                               __nv_bfloat16* __restrict__ lo,
                                               int n4, float scale)
{
    int i = blockIdx.x * 256 + threadIdx.x;
    if (i >= n4) return;
    float4 v = ((const float4*)in)[i];
    v.x *= scale; v.y *= scale; v.z *= scale; v.w *= scale;
    ((uint2*)hi)[i] = make_uint2(pack_hi(v.x, v.y), pack_hi(v.z, v.w));
    ((uint2*)lo)[i] = make_uint2(pack_lo(v.x, v.y), pack_lo(v.z, v.w));
}

// W[K][N] fp32 -> Wt_hi/lo[N][K] bf16 (tiled transpose)
__global__ __launch_bounds__(256) void tsplit_k(const float* __restrict__ W,
                                                __nv_bfloat16* __restrict__ Th,
                                                __nv_bfloat16* __restrict__ Tl,
                                                int K, int N)
{
    __shared__ float t[32][33];
    int tx = threadIdx.x, ty = threadIdx.y;   // 32 x 8
    int n0 = blockIdx.x * 32, k0 = blockIdx.y * 32;
#pragma unroll
    for (int i = 0; i < 4; i++)
        t[ty + 8 * i][tx] = W[(size_t)(k0 + ty + 8 * i) * N + n0 + tx];
    __syncthreads();
#pragma unroll
    for (int i = 0; i < 4; i++) {
        float v = t[tx][ty + 8 * i];
        store_bf_pair(Th, Tl, (size_t)(n0 + ty + 8 * i) * K + k0 + tx, v);
    }
}

// ---------------- HMMA GEMM, 2-stage cp.async, single-sync, 2 CTAs/SM -------
// mode 0: fp32 C+bias. mode 1: bf16 hi/lo (C+bias)*oscale.
// mode 2 (KV): K-half -> bf16 hi/lo [b,kvh,l,d]; V-half -> bf16 hi/lo TRANSPOSED
//              [b,kvh,d,l] directly (V2h/V2l), deleting the vtprep pass.
#define SSTRIDE 40
#define TILEB   10240u
#define STAGEB  (4u * TILEB)           // 40960 B per stage
#define GEMM_DSMEM (2 * (int)STAGEB)   // 81920 B

__global__ __launch_bounds__(256, 2) void hgemm_db_k(
    const __nv_bfloat16* __restrict__ Ah, const __nv_bfloat16* __restrict__ Al,
    const __nv_bfloat16* __restrict__ Bh, const __nv_bfloat16* __restrict__ Bl,
    const float* __restrict__ bias,
    float* __restrict__ C,
    __nv_bfloat16* __restrict__ Ch, __nv_bfloat16* __restrict__ Cl,
    __nv_bfloat16* __restrict__ V2h, __nv_bfloat16* __restrict__ V2l,
    float oscale, int M, int N, int K, int mode)
{
    extern __shared__ __nv_bfloat16 dynsm[];
    const uint32_t sbase = smem_u32(dynsm);

    const int tid  = threadIdx.x;
    const int wid  = tid >> 5, lane = tid & 31;
    const int gr   = lane >> 2, tg = lane & 3;
    const int wm   = (wid & 1) * 64;
    const int wn   = (wid >> 1) * 32;
    const int row0 = blockIdx.y * 128, col0 = blockIdx.x * 128;
    const int q    = lane >> 3, rr = lane & 7;

    float acc[4][4][4];
#pragma unroll
    for (int mt = 0; mt < 4; mt++)
#pragma unroll
        for (int nt = 0; nt < 4; nt++)
#pragma unroll
            for (int e = 0; e < 4; e++) acc[mt][nt][e] = 0.f;

    const int lr0 = tid >> 2, lc0 = (tid & 3) * 8;
    const int lr1 = lr0 + 64;
    const uint32_t so0 = (uint32_t)(lr0 * SSTRIDE + lc0) * 2;
    const uint32_t so1 = (uint32_t)(lr1 * SSTRIDE + lc0) * 2;
    const __nv_bfloat16* pAh = Ah + (size_t)row0 * K;
    const __nv_bfloat16* pAl = Al + (size_t)row0 * K;
    const __nv_bfloat16* pBh = Bh + (size_t)col0 * K;
    const __nv_bfloat16* pBl = Bl + (size_t)col0 * K;

    const int niter = K >> 5;

    auto issue = [&](uint32_t bb, int it) {
        const int kt = it << 5;
        CP16(bb + so0,              pAh + (size_t)lr0 * K + kt + lc0);
        CP16(bb + so1,              pAh + (size_t)lr1 * K + kt + lc0);
        CP16(bb + TILEB + so0,      pAl + (size_t)lr0 * K + kt + lc0);
        CP16(bb + TILEB + so1,      pAl + (size_t)lr1 * K + kt + lc0);
        CP16(bb + 2 * TILEB + so0,  pBh + (size_t)lr0 * K + kt + lc0);
        CP16(bb + 2 * TILEB + so1,  pBh + (size_t)lr1 * K + kt + lc0);
        CP16(bb + 3 * TILEB + so0,  pBl + (size_t)lr0 * K + kt + lc0);
        CP16(bb + 3 * TILEB + so1,  pBl + (size_t)lr1 * K + kt + lc0);
    };

    issue(sbase, 0); CP_COMMIT();

    uint32_t s = 0;
    for (int it = 0; it < niter; ++it) {
        CP_WAIT0();
        __syncthreads();
        if (it + 1 < niter) { issue(sbase + (s ^ STAGEB), it + 1); CP_COMMIT(); }

        const uint32_t aAh = sbase + s;
        const uint32_t aAl = aAh + TILEB;
        const uint32_t aBh = aAh + 2 * TILEB;
        const uint32_t aBl = aAh + 3 * TILEB;

#pragma unroll
        for (int ks = 0; ks < 2; ++ks) {
            uint32_t fBh0[4], fBh1[4], fBl0[4], fBl1[4];
            {
                uint32_t offb0 = (uint32_t)((wn + (q >> 1) * 8 + rr) * (SSTRIDE * 2)
                                            + (ks * 16 + (q & 1) * 8) * 2);
                uint32_t offb1 = offb0 + 16u * (SSTRIDE * 2);
                ldsm4(fBh0, aBh + offb0);
                ldsm4(fBh1, aBh + offb1);
                ldsm4(fBl0, aBl + offb0);
                ldsm4(fBl1, aBl + offb1);
            }
#pragma unroll
            for (int mt = 0; mt < 4; ++mt) {
                uint32_t offa = (uint32_t)((wm + mt * 16 + (q & 1) * 8 + rr) * (SSTRIDE * 2)
                                           + (ks * 16 + (q >> 1) * 8) * 2);
                uint32_t fA[4];
                ldsm4(fA, aAh + offa);
                mma16816(acc[mt][0], fA, &fBh0[0]);
                mma16816(acc[mt][1], fA, &fBh0[2]);
                mma16816(acc[mt][2], fA, &fBh1[0]);
                mma16816(acc[mt][3], fA, &fBh1[2]);
                mma16816(acc[mt][0], fA, &fBl0[0]);
                mma16816(acc[mt][1], fA, &fBl0[2]);
                mma16816(acc[mt][2], fA, &fBl1[0]);
                mma16816(acc[mt][3], fA, &fBl1[2]);
                uint32_t fA2[4];
                ldsm4(fA2, aAl + offa);
                mma16816(acc[mt][0], fA2, &fBh0[0]);
                mma16816(acc[mt][1], fA2, &fBh0[2]);
                mma16816(acc[mt][2], fA2, &fBh1[0]);
                mma16816(acc[mt][3], fA2, &fBh1[2]);
            }
        }
        s ^= STAGEB;
    }

    // ---- epilogue ----
    const bool kv_vpart = (mode == 2) && (col0 >= VW);
    if (kv_vpart) {
        // V: write transposed bf16 hi/lo to [b,kvh,d,l]
#pragma unroll
        for (int mt = 0; mt < 4; ++mt) {
#pragma unroll
            for (int nt = 0; nt < 4; ++nt) {
                int r = row0 + wm + mt * 16 + gr;
                int cfull = col0 + wn + nt * 8 + tg * 2;
                float b0 = bias[cfull], b1 = bias[cfull + 1];
                float v0 = acc[mt][nt][0] + b0;
                float v1 = acc[mt][nt][1] + b1;
                float v2 = acc[mt][nt][2] + b0;
                float v3 = acc[mt][nt][3] + b1;
                int c = cfull - VW;
                int kvhh = c >> 7, d = c & (HDIM_ - 1);
                int bb = r >> 11, ll = r & (L_ - 1);
                size_t base = ((size_t)(bb * NKV_ + kvhh) * HDIM_ + d) * L_;
                store_bf_pair(V2h, V2l, base + ll,          v0);
                store_bf_pair(V2h, V2l, base + L_ + ll,     v1);
                store_bf_pair(V2h, V2l, base + ll + 8,      v2);
                store_bf_pair(V2h, V2l, base + L_ + ll + 8, v3);
            }
        }
    } else if (mode == 1 || mode == 2) {
        // bf16 hi/lo output; for KV K-part, permute into [b,kvh,l,d]
#pragma unroll
        for (int mt = 0; mt < 4; ++mt) {
#pragma unroll
            for (int nt = 0; nt < 4; ++nt) {
                int r = row0 + wm + mt * 16 + gr;
                int c = col0 + wn + nt * 8 + tg * 2;
                float b0 = bias[c], b1 = bias[c + 1];
                float v0 = (acc[mt][nt][0] + b0) * oscale;
                float v1 = (acc[mt][nt][1] + b1) * oscale;
                float v2 = (acc[mt][nt][2] + b0) * oscale;
                float v3 = (acc[mt][nt][3] + b1) * oscale;
                size_t o0, o1;
                if (mode == 2) {
                    int bb = r >> 11, ll = r & (L_ - 1);
                    int kvhh = c >> 7, d = c & (HDIM_ - 1);
                    o0 = ((size_t)(bb * NKV_ + kvhh) * L_ + ll) * HDIM_ + d;
                    o1 = o0 + (size_t)8 * HDIM_;
                } else {
                    o0 = (size_t)r * N + c;
                    o1 = (size_t)(r + 8) * N + c;
                }
                *(uint32_t*)(Ch + o0) = pack_hi(v0, v1);
                *(uint32_t*)(Cl + o0) = pack_lo(v0, v1);
                *(uint32_t*)(Ch + o1) = pack_hi(v2, v3);
                *(uint32_t*)(Cl + o1) = pack_lo(v2, v3);
            }
        }
    } else {
#pragma unroll
        for (int mt = 0; mt < 4; ++mt) {
#pragma unroll
            for (int nt = 0; nt < 4; ++nt) {
                int r = row0 + wm + mt * 16 + gr;
                int c = col0 + wn + nt * 8 + tg * 2;
                float b0 = bias[c], b1 = bias[c + 1];
                float2 v0 = make_float2(acc[mt][nt][0] + b0, acc[mt][nt][1] + b1);
                float2 v1 = make_float2(acc[mt][nt][2] + b0, acc[mt][nt][3] + b1);
                *(float2*)(C + (size_t)r * N + c) = v0;
                *(float2*)(C + (size_t)(r + 8) * N + c) = v1;
            }
        }
    }
}

// ---------------------------------------------------------------------------
// Tensor-core flash attention — 64-q tile, 128 threads, register-resident Q,
// double-buffered V + mid-iteration K refill (copies overlap compute).
// Smem 108.5 KB -> 2 CTAs/SM.
// ---------------------------------------------------------------------------
#define QSTR 136
#define VSTR 72
#define KPAIR_B  (2u * 64 * QSTR * 2)        // 34816 B (Kh+Kl)
#define VPAIR_B  (2u * 128 * VSTR * 2)       // 36864 B (Vh+Vl) per stage
#define ATT_SMEM ((int)(KPAIR_B + 2 * VPAIR_B))   // 108544 B

__global__ __launch_bounds__(128, 2) void attn_tc_k(
    const __nv_bfloat16* __restrict__ Qh, const __nv_bfloat16* __restrict__ Ql,
    const __nv_bfloat16* __restrict__ Kh, const __nv_bfloat16* __restrict__ Kl,
    const __nv_bfloat16* __restrict__ Vh, const __nv_bfloat16* __restrict__ Vl,
    __nv_bfloat16* __restrict__ Oh, __nv_bfloat16* __restrict__ Ol)
{
    extern __shared__ __nv_bfloat16 smem_bf[];
    const uint32_t sb  = smem_u32(smem_bf);
    const uint32_t aKh = sb;                         // 64 x QSTR
    const uint32_t aKl = aKh + 64 * QSTR * 2;
    const uint32_t aV0 = aKl + 64 * QSTR * 2;        // V stage 0 (Vh, Vl)
    const uint32_t aV1 = aV0 + VPAIR_B;              // V stage 1

    const int b = blockIdx.z, head = blockIdx.y, qt = blockIdx.x;
    const int kvh = head >> 2;
    const int tid = threadIdx.x;
    const int wid = tid >> 5, lane = tid & 31;
    const int q = lane >> 3, rr = lane & 7;
    const int gr = lane >> 2, tg = lane & 3;

    const __nv_bfloat16* kbh = Kh + (size_t)(b * NKV_ + kvh) * L_ * HDIM_;
    const __nv_bfloat16* kbl = Kl + (size_t)(b * NKV_ + kvh) * L_ * HDIM_;
    const __nv_bfloat16* vbh = Vh + (size_t)(b * NKV_ + kvh) * HDIM_ * L_;
    const __nv_bfloat16* vbl = Vl + (size_t)(b * NKV_ + kvh) * HDIM_ * L_;

    // copy-index precomputes
    const int krow = tid >> 4, kch = (tid & 15);              // (with i*128 added)
    auto issueK = [&](int t) {
#pragma unroll
        for (int i = 0; i < 8; i++) {
            int idx = tid + i * 128;
            int row = idx >> 4, ch = idx & 15;
            uint32_t so = (uint32_t)(row * QSTR + ch * 8) * 2;
            CP16(aKh + so, kbh + (size_t)(t * 64 + row) * HDIM_ + ch * 8);
            CP16(aKl + so, kbl + (size_t)(t * 64 + row) * HDIM_ + ch * 8);
        }
    };
    auto issueV = [&](int t, uint32_t vb) {
#pragma unroll
        for (int i = 0; i < 8; i++) {
            int idx = tid + i * 128;
            int vrow = idx >> 3, vch = idx & 7;
            uint32_t so = (uint32_t)(vrow * VSTR + vch * 8) * 2;
            CP16(vb + so,                      vbh + (size_t)vrow * L_ + t * 64 + vch * 8);
            CP16(vb + 128 * VSTR * 2 + so,     vbl + (size_t)vrow * L_ + t * 64 + vch * 8);
        }
    };

    // ---- prologue: Q via K buffers -> registers ----
    {
        const __nv_bfloat16* qbh = Qh + (size_t)(b * L_ + qt * 64) * HID_ + head * HDIM_;
        const __nv_bfloat16* qbl = Ql + (size_t)(b * L_ + qt * 64) * HID_ + head * HDIM_;
#pragma unroll
        for (int i = 0; i < 8; i++) {
            int idx = tid + i * 128;
            int row = idx >> 4, ch = idx & 15;
            uint32_t so = (uint32_t)(row * QSTR + ch * 8) * 2;
            CP16(aKh + so, qbh + (size_t)row * HID_ + ch * 8);
            CP16(aKl + so, qbl + (size_t)row * HID_ + ch * 8);
        }
        CP_COMMIT(); CP_WAIT0();
    }
    __syncthreads();
    uint32_t fQh[8][4], fQl[8][4];
#pragma unroll
    for (int ks = 0; ks < 8; ++ks) {
        uint32_t aoff = (uint32_t)((wid * 16 + (q & 1) * 8 + rr) * (QSTR * 2)
                                   + (ks * 16 + (q >> 1) * 8) * 2);
        ldsm4(fQh[ks], aKh + aoff);
        ldsm4(fQl[ks], aKl + aoff);
    }
    __syncthreads();   // Q in registers before K(0) overwrites

    // first tiles in flight
    issueK(0); issueV(0, aV0); CP_COMMIT();

    float oacc[16][4];
#pragma unroll
    for (int nt = 0; nt < 16; nt++)
#pragma unroll
        for (int e = 0; e < 4; e++) oacc[nt][e] = 0.f;
    float m0 = -1e30f, m1 = -1e30f, l0 = 0.f, l1 = 0.f;

    const int NT = L_ / 64;
    for (int t = 0; t < NT; ++t) {
        const uint32_t vcur = (t & 1) ? aV1 : aV0;
        const uint32_t vnxt = (t & 1) ? aV0 : aV1;

        CP_WAIT0();          // K(t) + V(t) (and early-arrived extras) landed
        __syncthreads();     // visibility + all warps done with prior buffers

        if (t + 1 < NT) { issueV(t + 1, vnxt); CP_COMMIT(); }  // overlaps everything

        // ---- S = Q K^T (16 x 64 per warp), 3-term, Q from registers ----
        float sacc[8][4];
#pragma unroll
        for (int nt = 0; nt < 8; nt++)
#pragma unroll
            for (int e = 0; e < 4; e++) sacc[nt][e] = 0.f;

#pragma unroll
        for (int ks = 0; ks < 8; ++ks) {
            uint32_t fKh[4][4], fKl[4][4];
#pragma unroll
            for (int np = 0; np < 4; ++np) {
                uint32_t boff = (uint32_t)((np * 16 + (q >> 1) * 8 + rr) * (QSTR * 2)
                                           + (ks * 16 + (q & 1) * 8) * 2);
                ldsm4(fKh[np], aKh + boff);
                ldsm4(fKl[np], aKl + boff);
            }
#pragma unroll
            for (int nt = 0; nt < 8; ++nt) {
                const uint32_t* bh = &fKh[nt >> 1][(nt & 1) * 2];
                const uint32_t* bl = &fKl[nt >> 1][(nt & 1) * 2];
                mma16816(sacc[nt], fQh[ks], bh);
                mma16816(sacc[nt], fQl[ks], bh);
                mma16816(sacc[nt], fQh[ks], bl);
            }
        }
        __syncthreads();     // all warps done reading K buffer
        if (t + 1 < NT) { issueK(t + 1); CP_COMMIT(); }  // overlaps softmax + PV

        // ---- online softmax ----
        float rmax0 = -1e30f, rmax1 = -1e30f;
#pragma unroll
        for (int nt = 0; nt < 8; ++nt) {
            rmax0 = fmaxf(rmax0, fmaxf(sacc[nt][0], sacc[nt][1]));
            rmax1 = fmaxf(rmax1, fmaxf(sacc[nt][2], sacc[nt][3]));
        }
        rmax0 = fmaxf(rmax0, __shfl_xor_sync(0xffffffffu, rmax0, 1));
        rmax0 = fmaxf(rmax0, __shfl_xor_sync(0xffffffffu, rmax0, 2));
        rmax1 = fmaxf(rmax1, __shfl_xor_sync(0xffffffffu, rmax1, 1));
        rmax1 = fmaxf(rmax1, __shfl_xor_sync(0xffffffffu, rmax1, 2));
        float mn0 = fmaxf(m0, rmax0), mn1 = fmaxf(m1, rmax1);
        float fact0 = __expf(m0 - mn0), fact1 = __expf(m1 - mn1);
        m0 = mn0; m1 = mn1;
        float sum0 = 0.f, sum1 = 0.f;
#pragma unroll
        for (int nt = 0; nt < 8; ++nt) {
            sacc[nt][0] = __expf(sacc[nt][0] - mn0); sum0 += sacc[nt][0];
            sacc[nt][1] = __expf(sacc[nt][1] - mn0); sum0 += sacc[nt][1];
            sacc[nt][2] = __expf(sacc[nt][2] - mn1); sum1 += sacc[nt][2];
            sacc[nt][3] = __expf(sacc[nt][3] - mn1); sum1 += sacc[nt][3];
        }
        sum0 += __shfl_xor_sync(0xffffffffu, sum0, 1);
        sum0 += __shfl_xor_sync(0xffffffffu, sum0, 2);
        sum1 += __shfl_xor_sync(0xffffffffu, sum1, 1);
        sum1 += __shfl_xor_sync(0xffffffffu, sum1, 2);
        l0 = l0 * fact0 + sum0;
        l1 = l1 * fact1 + sum1;
#pragma unroll
        for (int nt = 0; nt < 16; ++nt) {
            oacc[nt][0] *= fact0; oacc[nt][1] *= fact0;
            oacc[nt][2] *= fact1; oacc[nt][3] *= fact1;
        }

        // ---- O += P V (V from vcur), 3-term ----
        const uint32_t aVhc = vcur, aVlc = vcur + 128 * VSTR * 2;
#pragma unroll
        for (int j = 0; j < 4; ++j) {
            uint32_t aPh[4], aPl[4];
#pragma unroll
            for (int hlf = 0; hlf < 2; ++hlf) {
                const float* p = sacc[2 * j + hlf];
                aPh[2 * hlf]     = pack_hi(p[0], p[1]);
                aPh[2 * hlf + 1] = pack_hi(p[2], p[3]);
                aPl[2 * hlf]     = pack_lo(p[0], p[1]);
                aPl[2 * hlf + 1] = pack_lo(p[2], p[3]);
            }
#pragma unroll
            for (int nn = 0; nn < 8; ++nn) {
                uint32_t fVh[4], fVl[4];
                uint32_t voff = (uint32_t)((nn * 16 + (q >> 1) * 8 + rr) * (VSTR * 2)
                                           + (j * 16 + (q & 1) * 8) * 2);
                ldsm4(fVh, aVhc + voff);
                ldsm4(fVl, aVlc + voff);
                mma16816(oacc[2 * nn], aPh, &fVh[0]);
                mma16816(oacc[2 * nn], aPl, &fVh[0]);
                mma16816(oacc[2 * nn], aPh, &fVl[0]);
                mma16816(oacc[2 * nn + 1], aPh, &fVh[2]);
                mma16816(oacc[2 * nn + 1], aPl, &fVh[2]);
                mma16816(oacc[2 * nn + 1], aPh, &fVl[2]);
            }
        }
    }

    // ---- normalize + store O as bf16 hi/lo ----
    float inv0 = 1.0f / l0, inv1 = 1.0f / l1;
    const int row0g = b * L_ + qt * 64 + wid * 16 + gr;
    __nv_bfloat16* oh0 = Oh + (size_t)row0g * HID_ + head * HDIM_;
    __nv_bfloat16* ol0 = Ol + (size_t)row0g * HID_ + head * HDIM_;
    __nv_bfloat16* oh1 = oh0 + (size_t)8 * HID_;
    __nv_bfloat16* ol1 = ol0 + (size_t)8 * HID_;
#pragma unroll
    for (int nt = 0; nt < 16; ++nt) {
        int col = nt * 8 + tg * 2;
        float v0 = oacc[nt][0] * inv0, v1 = oacc[nt][1] * inv0;
        float v2 = oacc[nt][2] * inv1, v3 = oacc[nt][3] * inv1;
        *(uint32_t*)(oh0 + col) = pack_hi(v0, v1);
        *(uint32_t*)(ol0 + col) = pack_lo(v0, v1);
        *(uint32_t*)(oh1 + col) = pack_hi(v2, v3);
        *(uint32_t*)(ol1 + col) = pack_lo(v2, v3);
    }
}

// ---------------------------------------------------------------------------
extern "C" void kernel_launch(void* const* d_in, const int* in_sizes, int n_in,
                              void* d_out, int out_size)
{
    const float* query = (const float*)d_in[0];
    const float* kv    = (const float*)d_in[1];
    const float* Wq    = (const float*)d_in[2];
    const float* bq    = (const float*)d_in[3];
    const float* Wkv   = (const float*)d_in[4];
    const float* bkv   = (const float*)d_in[5];
    const float* Wo    = (const float*)d_in[6];
    const float* bo    = (const float*)d_in[7];
    float* out = (float*)d_out;

    __nv_bfloat16 *qh, *ql, *kvh, *kvl, *ath, *atl;
    __nv_bfloat16 *wqh, *wql, *wkh, *wkl, *woh, *wol;
    __nv_bfloat16 *aqh, *aql, *akh, *akl, *avh, *avl;
    cudaGetSymbolAddress((void**)&qh,  g_qin_h);  cudaGetSymbolAddress((void**)&ql,  g_qin_l);
    cudaGetSymbolAddress((void**)&kvh, g_kvin_h); cudaGetSymbolAddress((void**)&kvl, g_kvin_l);
    cudaGetSymbolAddress((void**)&ath, g_att_h);  cudaGetSymbolAddress((void**)&atl, g_att_l);
    cudaGetSymbolAddress((void**)&wqh, g_wqt_h);  cudaGetSymbolAddress((void**)&wql, g_wqt_l);
    cudaGetSymbolAddress((void**)&wkh, g_wkvt_h); cudaGetSymbolAddress((void**)&wkl, g_wkvt_l);
    cudaGetSymbolAddress((void**)&woh, g_wot_h);  cudaGetSymbolAddress((void**)&wol, g_wot_l);
    cudaGetSymbolAddress((void**)&aqh, g_aqh);    cudaGetSymbolAddress((void**)&aql, g_aql);
    cudaGetSymbolAddress((void**)&akh, g_kh);     cudaGetSymbolAddress((void**)&akl, g_kl);
    cudaGetSymbolAddress((void**)&avh, g_vth);    cudaGetSymbolAddress((void**)&avl, g_vtl);

    cudaFuncSetAttribute(attn_tc_k, cudaFuncAttributeMaxDynamicSharedMemorySize,
                         ATT_SMEM);
    cudaFuncSetAttribute(hgemm_db_k, cudaFuncAttributeMaxDynamicSharedMemorySize,
                         GEMM_DSMEM);

    const int n_act4 = (MROWS * HID_) / 4;
    const float qscale = 0.08838834764831845f;   // 1/sqrt(128)

    split_k<<<(n_act4 + 255) / 256, 256>>>(query, qh, ql, n_act4, 1.0f);            // 0
    tsplit_k<<<dim3(HID_ / 32, HID_ / 32), dim3(32, 8)>>>(Wq, wqh, wql, HID_, HID_); // 1
    split_k<<<(n_act4 + 255) / 256, 256>>>(kv, kvh, kvl, n_act4, 1.0f);             // 2
    // 3: Q projection -> scaled bf16 hi/lo (ncu capture slot)
    hgemm_db_k<<<dim3(HID_ / 128, MROWS / 128), 256, GEMM_DSMEM>>>(
        qh, ql, wqh, wql, bq, nullptr, aqh, aql, nullptr, nullptr,
        qscale, MROWS, HID_, HID_, 1);
    tsplit_k<<<dim3(KVW / 32, HID_ / 32), dim3(32, 8)>>>(Wkv, wkh, wkl, HID_, KVW); // 4
    // 5: KV projection -> K [b,kvh,l,d] + V transposed [b,kvh,d,l], all bf16 hi/lo
    hgemm_db_k<<<dim3(KVW / 128, MROWS / 128), 256, GEMM_DSMEM>>>(
        kvh, kvl, wkh, wkl, bkv, nullptr, akh, akl, avh, avl,
        1.0f, MROWS, KVW, HID_, 2);
    tsplit_k<<<dim3(HID_ / 32, HID_ / 32), dim3(32, 8)>>>(Wo, woh, wol, HID_, HID_); // 6
    // 7: tensor-core attention (double-buffered V, overlapped K refill)
    attn_tc_k<<<dim3(L_ / 64, NHEAD_, B_), 128, ATT_SMEM>>>(
        aqh, aql, akh, akl, avh, avl, ath, atl);
    // 8: O projection -> fp32 out
    hgemm_db_k<<<dim3(HID_ / 128, MROWS / 128), 256, GEMM_DSMEM>>>(
        ath, atl, woh, wol, bo, out, nullptr, nullptr, nullptr, nullptr,
        1.0f, MROWS, HID_, HID_, 0);
}

// round 12
// speedup vs baseline: 1.5453x; 1.5453x over previous
#include <cuda_runtime.h>
#include <cuda_bf16.h>
#include <cstdint>
#include <math.h>

#define B_     2
#define L_     2048
#define HID_   4096
#define NHEAD_ 32
#define NKV_   8
#define HDIM_  128
#define MROWS  (B_*L_)          // 4096
#define KVW    (2*NKV_*HDIM_)   // 2048
#define VW     (NKV_*HDIM_)     // 1024

// ------------------------- device scratch (no allocs) -----------------------
__device__ __align__(256) float g_v  [(size_t)MROWS * VW];   // V fp32 (16 MB)

__device__ __align__(256) __nv_bfloat16 g_qin_h [(size_t)MROWS * HID_];
__device__ __align__(256) __nv_bfloat16 g_qin_l [(size_t)MROWS * HID_];
__device__ __align__(256) __nv_bfloat16 g_kvin_h[(size_t)MROWS * HID_];
__device__ __align__(256) __nv_bfloat16 g_kvin_l[(size_t)MROWS * HID_];
__device__ __align__(256) __nv_bfloat16 g_att_h [(size_t)MROWS * HID_];
__device__ __align__(256) __nv_bfloat16 g_att_l [(size_t)MROWS * HID_];
__device__ __align__(256) __nv_bfloat16 g_wqt_h [(size_t)HID_ * HID_];
__device__ __align__(256) __nv_bfloat16 g_wqt_l [(size_t)HID_ * HID_];
__device__ __align__(256) __nv_bfloat16 g_wkvt_h[(size_t)KVW  * HID_];
__device__ __align__(256) __nv_bfloat16 g_wkvt_l[(size_t)KVW  * HID_];
__device__ __align__(256) __nv_bfloat16 g_wot_h [(size_t)HID_ * HID_];
__device__ __align__(256) __nv_bfloat16 g_wot_l [(size_t)HID_ * HID_];
// attention operands (bf16 hi/lo)
__device__ __align__(256) __nv_bfloat16 g_aqh[(size_t)MROWS * HID_];  // scaled Q
__device__ __align__(256) __nv_bfloat16 g_aql[(size_t)MROWS * HID_];
__device__ __align__(256) __nv_bfloat16 g_kh [(size_t)B_*NKV_*L_*HDIM_]; // [b,kvh,l,d]
__device__ __align__(256) __nv_bfloat16 g_kl [(size_t)B_*NKV_*L_*HDIM_];
__device__ __align__(256) __nv_bfloat16 g_vth[(size_t)B_*NKV_*HDIM_*L_]; // [b,kvh,d,l]
__device__ __align__(256) __nv_bfloat16 g_vtl[(size_t)B_*NKV_*HDIM_*L_];

// ------------------------------ PTX helpers ---------------------------------
__device__ __forceinline__ uint32_t smem_u32(const void* p) {
    uint32_t a;
    asm("{ .reg .u64 t; cvta.to.shared.u64 t, %1; cvt.u32.u64 %0, t; }"
        : "=r"(a) : "l"(p));
    return a;
}

__device__ __forceinline__ void ldsm4(uint32_t* r, uint32_t addr) {
    asm volatile("ldmatrix.sync.aligned.m8n8.x4.shared.b16 {%0,%1,%2,%3}, [%4];"
                 : "=r"(r[0]), "=r"(r[1]), "=r"(r[2]), "=r"(r[3]) : "r"(addr));
}

__device__ __forceinline__ void mma16816(float* d, const uint32_t* a,
                                         const uint32_t* b) {
    asm volatile(
        "mma.sync.aligned.m16n8k16.row.col.f32.bf16.bf16.f32 "
        "{%0,%1,%2,%3}, {%4,%5,%6,%7}, {%8,%9}, {%0,%1,%2,%3};"
        : "+f"(d[0]), "+f"(d[1]), "+f"(d[2]), "+f"(d[3])
        : "r"(a[0]), "r"(a[1]), "r"(a[2]), "r"(a[3]), "r"(b[0]), "r"(b[1]));
}

#define CP16(saddr, gaddr) \
    asm volatile("cp.async.cg.shared.global [%0], [%1], 16;" \
                 :: "r"(saddr), "l"(gaddr) : "memory")
#define CP_COMMIT()  asm volatile("cp.async.commit_group;" ::: "memory")
#define CP_WAIT0()   asm volatile("cp.async.wait_group 0;" ::: "memory")

__device__ __forceinline__ unsigned short f2bf_bits(float x) {
    __nv_bfloat16 h = __float2bfloat16(x);
    return *(unsigned short*)&h;
}
__device__ __forceinline__ float bf_bits2f(unsigned short b) {
    __nv_bfloat16 h = *(__nv_bfloat16*)&b;
    return __bfloat162float(h);
}
__device__ __forceinline__ uint32_t pack_hi(float a, float b) {
    return (uint32_t)f2bf_bits(a) | ((uint32_t)f2bf_bits(b) << 16);
}
__device__ __forceinline__ uint32_t pack_lo(float a, float b) {
    unsigned short ha = f2bf_bits(a), hb = f2bf_bits(b);
    return (uint32_t)f2bf_bits(a - bf_bits2f(ha))
         | ((uint32_t)f2bf_bits(b - bf_bits2f(hb)) << 16);
}

// ---------------------------- conversion kernels ----------------------------
__global__ __launch_bounds__(256) void split_k(const float* __restrict__ in,
                                               __nv_bfloat16* __restrict__ hi,
                                               __nv_bfloat16* __restrict__ lo,
                                               int n4, float scale)
{
    int i = blockIdx.x * 256 + threadIdx.x;
    if (i >= n4) return;
    float4 v = ((const float4*)in)[i];
    v.x *= scale; v.y *= scale; v.z *= scale; v.w *= scale;
    ((uint2*)hi)[i] = make_uint2(pack_hi(v.x, v.y), pack_hi(v.z, v.w));
    ((uint2*)lo)[i] = make_uint2(pack_lo(v.x, v.y), pack_lo(v.z, v.w));
}

// W[K][N] fp32 -> Wt_hi/lo[N][K] bf16 (tiled transpose)
__global__ __launch_bounds__(256) void tsplit_k(const float* __restrict__ W,
                                                __nv_bfloat16* __restrict__ Th,
                                                __nv_bfloat16* __restrict__ Tl,
                                                int K, int N)
{
    __shared__ float t[32][33];
    int tx = threadIdx.x, ty = threadIdx.y;   // 32 x 8
    int n0 = blockIdx.x * 32, k0 = blockIdx.y * 32;
#pragma unroll
    for (int i = 0; i < 4; i++)
        t[ty + 8 * i][tx] = W[(size_t)(k0 + ty + 8 * i) * N + n0 + tx];
    __syncthreads();
#pragma unroll
    for (int i = 0; i < 4; i++) {
        float v = t[tx][ty + 8 * i];
        unsigned short h = f2bf_bits(v);
        unsigned short l = f2bf_bits(v - bf_bits2f(h));
        size_t o = (size_t)(n0 + ty + 8 * i) * K + k0 + tx;
        Th[o] = *(__nv_bfloat16*)&h; Tl[o] = *(__nv_bfloat16*)&l;
    }
}

// V prep: g_v fp32 [b*L+l][kvh*128+d] -> vth/vtl [b,kvh,d,l] bf16 (transpose)
__global__ __launch_bounds__(256) void vtprep_k(const float* __restrict__ V,
                                                __nv_bfloat16* __restrict__ Vh,
                                                __nv_bfloat16* __restrict__ Vl)
{
    __shared__ float t[32][33];
    int tx = threadIdx.x, ty = threadIdx.y;
    int l0 = blockIdx.x * 32, d0 = blockIdx.y * 32;
    int bk = blockIdx.z;
    int b = bk >> 3, kvh = bk & 7;
#pragma unroll
    for (int i = 0; i < 4; i++)
        t[ty + 8 * i][tx] = V[(size_t)(b * L_ + l0 + ty + 8 * i) * VW
                              + kvh * HDIM_ + d0 + tx];
    __syncthreads();
#pragma unroll
    for (int i = 0; i < 4; i++) {
        float v = t[tx][ty + 8 * i];
        unsigned short h = f2bf_bits(v);
        unsigned short l = f2bf_bits(v - bf_bits2f(h));
        size_t o = ((size_t)bk * HDIM_ + d0 + ty + 8 * i) * L_ + l0 + tx;
        Vh[o] = *(__nv_bfloat16*)&h; Vl[o] = *(__nv_bfloat16*)&l;
    }
}

// ---------------- HMMA GEMM, 2-stage cp.async, single-sync, 2 CTAs/SM -------
// (byte-identical to the validated Round-10 kernel)
#define SSTRIDE 40
#define TILEB   10240u
#define STAGEB  (4u * TILEB)           // 40960 B per stage
#define GEMM_DSMEM (2 * (int)STAGEB)   // 81920 B

__global__ __launch_bounds__(256, 2) void hgemm_db_k(
    const __nv_bfloat16* __restrict__ Ah, const __nv_bfloat16* __restrict__ Al,
    const __nv_bfloat16* __restrict__ Bh, const __nv_bfloat16* __restrict__ Bl,
    const float* __restrict__ bias,
    float* __restrict__ C,
    __nv_bfloat16* __restrict__ Ch, __nv_bfloat16* __restrict__ Cl,
    float oscale, int M, int N, int K, int mode)
{
    extern __shared__ __nv_bfloat16 dynsm[];
    const uint32_t sbase = smem_u32(dynsm);

    const int tid  = threadIdx.x;
    const int wid  = tid >> 5, lane = tid & 31;
    const int gr   = lane >> 2, tg = lane & 3;
    const int wm   = (wid & 1) * 64;
    const int wn   = (wid >> 1) * 32;
    const int row0 = blockIdx.y * 128, col0 = blockIdx.x * 128;
    const int q    = lane >> 3, rr = lane & 7;

    float acc[4][4][4];
#pragma unroll
    for (int mt = 0; mt < 4; mt++)
#pragma unroll
        for (int nt = 0; nt < 4; nt++)
#pragma unroll
            for (int e = 0; e < 4; e++) acc[mt][nt][e] = 0.f;

    const int lr0 = tid >> 2, lc0 = (tid & 3) * 8;
    const int lr1 = lr0 + 64;
    const uint32_t so0 = (uint32_t)(lr0 * SSTRIDE + lc0) * 2;
    const uint32_t so1 = (uint32_t)(lr1 * SSTRIDE + lc0) * 2;
    const __nv_bfloat16* pAh = Ah + (size_t)row0 * K;
    const __nv_bfloat16* pAl = Al + (size_t)row0 * K;
    const __nv_bfloat16* pBh = Bh + (size_t)col0 * K;
    const __nv_bfloat16* pBl = Bl + (size_t)col0 * K;

    const int niter = K >> 5;

    auto issue = [&](uint32_t bb, int it) {
        const int kt = it << 5;
        CP16(bb + so0,              pAh + (size_t)lr0 * K + kt + lc0);
        CP16(bb + so1,              pAh + (size_t)lr1 * K + kt + lc0);
        CP16(bb + TILEB + so0,      pAl + (size_t)lr0 * K + kt + lc0);
        CP16(bb + TILEB + so1,      pAl + (size_t)lr1 * K + kt + lc0);
        CP16(bb + 2 * TILEB + so0,  pBh + (size_t)lr0 * K + kt + lc0);
        CP16(bb + 2 * TILEB + so1,  pBh + (size_t)lr1 * K + kt + lc0);
        CP16(bb + 3 * TILEB + so0,  pBl + (size_t)lr0 * K + kt + lc0);
        CP16(bb + 3 * TILEB + so1,  pBl + (size_t)lr1 * K + kt + lc0);
    };

    issue(sbase, 0); CP_COMMIT();

    uint32_t s = 0;
    for (int it = 0; it < niter; ++it) {
        CP_WAIT0();
        __syncthreads();
        if (it + 1 < niter) { issue(sbase + (s ^ STAGEB), it + 1); CP_COMMIT(); }

        const uint32_t aAh = sbase + s;
        const uint32_t aAl = aAh + TILEB;
        const uint32_t aBh = aAh + 2 * TILEB;
        const uint32_t aBl = aAh + 3 * TILEB;

#pragma unroll
        for (int ks = 0; ks < 2; ++ks) {
            uint32_t fBh0[4], fBh1[4], fBl0[4], fBl1[4];
            {
                uint32_t offb0 = (uint32_t)((wn + (q >> 1) * 8 + rr) * (SSTRIDE * 2)
                                            + (ks * 16 + (q & 1) * 8) * 2);
                uint32_t offb1 = offb0 + 16u * (SSTRIDE * 2);
                ldsm4(fBh0, aBh + offb0);
                ldsm4(fBh1, aBh + offb1);
                ldsm4(fBl0, aBl + offb0);
                ldsm4(fBl1, aBl + offb1);
            }
#pragma unroll
            for (int mt = 0; mt < 4; ++mt) {
                uint32_t offa = (uint32_t)((wm + mt * 16 + (q & 1) * 8 + rr) * (SSTRIDE * 2)
                                           + (ks * 16 + (q >> 1) * 8) * 2);
                uint32_t fA[4];
                ldsm4(fA, aAh + offa);
                mma16816(acc[mt][0], fA, &fBh0[0]);
                mma16816(acc[mt][1], fA, &fBh0[2]);
                mma16816(acc[mt][2], fA, &fBh1[0]);
                mma16816(acc[mt][3], fA, &fBh1[2]);
                mma16816(acc[mt][0], fA, &fBl0[0]);
                mma16816(acc[mt][1], fA, &fBl0[2]);
                mma16816(acc[mt][2], fA, &fBl1[0]);
                mma16816(acc[mt][3], fA, &fBl1[2]);
                uint32_t fA2[4];
                ldsm4(fA2, aAl + offa);
                mma16816(acc[mt][0], fA2, &fBh0[0]);
                mma16816(acc[mt][1], fA2, &fBh0[2]);
                mma16816(acc[mt][2], fA2, &fBh1[0]);
                mma16816(acc[mt][3], fA2, &fBh1[2]);
            }
        }
        s ^= STAGEB;
    }

    // ---- epilogue ----
    const bool kv_kpart = (mode == 2) && (col0 < VW);
    if (mode == 1 || kv_kpart) {
#pragma unroll
        for (int mt = 0; mt < 4; ++mt) {
#pragma unroll
            for (int nt = 0; nt < 4; ++nt) {
                int r = row0 + wm + mt * 16 + gr;
                int c = col0 + wn + nt * 8 + tg * 2;
                float b0 = bias[c], b1 = bias[c + 1];
                float v0 = (acc[mt][nt][0] + b0) * oscale;
                float v1 = (acc[mt][nt][1] + b1) * oscale;
                float v2 = (acc[mt][nt][2] + b0) * oscale;
                float v3 = (acc[mt][nt][3] + b1) * oscale;
                size_t o0, o1;
                if (kv_kpart) {
                    int bb = r >> 11, ll = r & (L_ - 1);
                    int kvhh = c >> 7, d = c & (HDIM_ - 1);
                    o0 = ((size_t)(bb * NKV_ + kvhh) * L_ + ll) * HDIM_ + d;
                    o1 = o0 + (size_t)8 * HDIM_;
                } else {
                    o0 = (size_t)r * N + c;
                    o1 = (size_t)(r + 8) * N + c;
                }
                *(uint32_t*)(Ch + o0) = pack_hi(v0, v1);
                *(uint32_t*)(Cl + o0) = pack_lo(v0, v1);
                *(uint32_t*)(Ch + o1) = pack_hi(v2, v3);
                *(uint32_t*)(Cl + o1) = pack_lo(v2, v3);
            }
        }
    } else {
        const int cw    = (mode == 2) ? VW : N;
        const int cbase = (mode == 2) ? (col0 - VW) : col0;
#pragma unroll
        for (int mt = 0; mt < 4; ++mt) {
#pragma unroll
            for (int nt = 0; nt < 4; ++nt) {
                int r = row0 + wm + mt * 16 + gr;
                int c = col0 + wn + nt * 8 + tg * 2;
                float b0 = bias[c], b1 = bias[c + 1];
                int cc = cbase + wn + nt * 8 + tg * 2;
                float2 v0 = make_float2(acc[mt][nt][0] + b0, acc[mt][nt][1] + b1);
                float2 v1 = make_float2(acc[mt][nt][2] + b0, acc[mt][nt][3] + b1);
                *(float2*)(C + (size_t)r * cw + cc) = v0;
                *(float2*)(C + (size_t)(r + 8) * cw + cc) = v1;
            }
        }
    }
}

// ---------------------------------------------------------------------------
// Tensor-core flash attention — 64-q tile, 128 threads, register-resident Q,
// double-buffered V + mid-iteration K refill (copies overlap compute).
// Smem 108.5 KB -> 2 CTAs/SM (same occupancy as R10's version).
// ---------------------------------------------------------------------------
#define QSTR 136
#define VSTR 72
#define KPAIR_B  (2u * 64 * QSTR * 2)        // 34816 B (Kh+Kl)
#define VPAIR_B  (2u * 128 * VSTR * 2)       // 36864 B (Vh+Vl) per stage
#define ATT_SMEM ((int)(KPAIR_B + 2 * VPAIR_B))   // 108544 B

__global__ __launch_bounds__(128) void attn_tc_k(
    const __nv_bfloat16* __restrict__ Qh, const __nv_bfloat16* __restrict__ Ql,
    const __nv_bfloat16* __restrict__ Kh, const __nv_bfloat16* __restrict__ Kl,
    const __nv_bfloat16* __restrict__ Vh, const __nv_bfloat16* __restrict__ Vl,
    __nv_bfloat16* __restrict__ Oh, __nv_bfloat16* __restrict__ Ol)
{
    extern __shared__ __nv_bfloat16 smem_bf[];
    const uint32_t sb  = smem_u32(smem_bf);
    const uint32_t aKh = sb;                         // 64 x QSTR
    const uint32_t aKl = aKh + 64 * QSTR * 2;
    const uint32_t aV0 = aKl + 64 * QSTR * 2;        // V stage 0 (Vh, Vl)
    const uint32_t aV1 = aV0 + VPAIR_B;              // V stage 1

    const int b = blockIdx.z, head = blockIdx.y, qt = blockIdx.x;
    const int kvh = head >> 2;
    const int tid = threadIdx.x;
    const int wid = tid >> 5, lane = tid & 31;
    const int q = lane >> 3, rr = lane & 7;
    const int gr = lane >> 2, tg = lane & 3;

    const __nv_bfloat16* kbh = Kh + (size_t)(b * NKV_ + kvh) * L_ * HDIM_;
    const __nv_bfloat16* kbl = Kl + (size_t)(b * NKV_ + kvh) * L_ * HDIM_;
    const __nv_bfloat16* vbh = Vh + (size_t)(b * NKV_ + kvh) * HDIM_ * L_;
    const __nv_bfloat16* vbl = Vl + (size_t)(b * NKV_ + kvh) * HDIM_ * L_;

    auto issueK = [&](int t) {
#pragma unroll
        for (int i = 0; i < 8; i++) {
            int idx = tid + i * 128;
            int row = idx >> 4, ch = idx & 15;
            uint32_t so = (uint32_t)(row * QSTR + ch * 8) * 2;
            CP16(aKh + so, kbh + (size_t)(t * 64 + row) * HDIM_ + ch * 8);
            CP16(aKl + so, kbl + (size_t)(t * 64 + row) * HDIM_ + ch * 8);
        }
    };
    auto issueV = [&](int t, uint32_t vb) {
#pragma unroll
        for (int i = 0; i < 8; i++) {
            int idx = tid + i * 128;
            int vrow = idx >> 3, vch = idx & 7;
            uint32_t so = (uint32_t)(vrow * VSTR + vch * 8) * 2;
            CP16(vb + so,                   vbh + (size_t)vrow * L_ + t * 64 + vch * 8);
            CP16(vb + 128 * VSTR * 2 + so,  vbl + (size_t)vrow * L_ + t * 64 + vch * 8);
        }
    };

    // ---- prologue: Q via K buffers -> registers ----
    {
        const __nv_bfloat16* qbh = Qh + (size_t)(b * L_ + qt * 64) * HID_ + head * HDIM_;
        const __nv_bfloat16* qbl = Ql + (size_t)(b * L_ + qt * 64) * HID_ + head * HDIM_;
#pragma unroll
        for (int i = 0; i < 8; i++) {
            int idx = tid + i * 128;
            int row = idx >> 4, ch = idx & 15;
            uint32_t so = (uint32_t)(row * QSTR + ch * 8) * 2;
            CP16(aKh + so, qbh + (size_t)row * HID_ + ch * 8);
            CP16(aKl + so, qbl + (size_t)row * HID_ + ch * 8);
        }
        CP_COMMIT(); CP_WAIT0();
    }
    __syncthreads();
    uint32_t fQh[8][4], fQl[8][4];
#pragma unroll
    for (int ks = 0; ks < 8; ++ks) {
        uint32_t aoff = (uint32_t)((wid * 16 + (q & 1) * 8 + rr) * (QSTR * 2)
                                   + (ks * 16 + (q >> 1) * 8) * 2);
        ldsm4(fQh[ks], aKh + aoff);
        ldsm4(fQl[ks], aKl + aoff);
    }
    __syncthreads();   // Q in registers before K(0) overwrites

    issueK(0); issueV(0, aV0); CP_COMMIT();

    float oacc[16][4];
#pragma unroll
    for (int nt = 0; nt < 16; nt++)
#pragma unroll
        for (int e = 0; e < 4; e++) oacc[nt][e] = 0.f;
    float m0 = -1e30f, m1 = -1e30f, l0 = 0.f, l1 = 0.f;

    const int NT = L_ / 64;
    for (int t = 0; t < NT; ++t) {
        const uint32_t vcur = (t & 1) ? aV1 : aV0;
        const uint32_t vnxt = (t & 1) ? aV0 : aV1;

        CP_WAIT0();          // K(t) + V(t) landed
        __syncthreads();

        if (t + 1 < NT) { issueV(t + 1, vnxt); CP_COMMIT(); }  // overlaps everything

        // ---- S = Q K^T, 3-term, Q from registers ----
        float sacc[8][4];
#pragma unroll
        for (int nt = 0; nt < 8; nt++)
#pragma unroll
            for (int e = 0; e < 4; e++) sacc[nt][e] = 0.f;

#pragma unroll
        for (int ks = 0; ks < 8; ++ks) {
            uint32_t fKh[4][4], fKl[4][4];
#pragma unroll
            for (int np = 0; np < 4; ++np) {
                uint32_t boff = (uint32_t)((np * 16 + (q >> 1) * 8 + rr) * (QSTR * 2)
                                           + (ks * 16 + (q & 1) * 8) * 2);
                ldsm4(fKh[np], aKh + boff);
                ldsm4(fKl[np], aKl + boff);
            }
#pragma unroll
            for (int nt = 0; nt < 8; ++nt) {
                const uint32_t* bh = &fKh[nt >> 1][(nt & 1) * 2];
                const uint32_t* bl = &fKl[nt >> 1][(nt & 1) * 2];
                mma16816(sacc[nt], fQh[ks], bh);
                mma16816(sacc[nt], fQl[ks], bh);
                mma16816(sacc[nt], fQh[ks], bl);
            }
        }
        __syncthreads();     // all warps done reading K buffer
        if (t + 1 < NT) { issueK(t + 1); CP_COMMIT(); }  // overlaps softmax + PV

        // ---- online softmax ----
        float rmax0 = -1e30f, rmax1 = -1e30f;
#pragma unroll
        for (int nt = 0; nt < 8; ++nt) {
            rmax0 = fmaxf(rmax0, fmaxf(sacc[nt][0], sacc[nt][1]));
            rmax1 = fmaxf(rmax1, fmaxf(sacc[nt][2], sacc[nt][3]));
        }
        rmax0 = fmaxf(rmax0, __shfl_xor_sync(0xffffffffu, rmax0, 1));
        rmax0 = fmaxf(rmax0, __shfl_xor_sync(0xffffffffu, rmax0, 2));
        rmax1 = fmaxf(rmax1, __shfl_xor_sync(0xffffffffu, rmax1, 1));
        rmax1 = fmaxf(rmax1, __shfl_xor_sync(0xffffffffu, rmax1, 2));
        float mn0 = fmaxf(m0, rmax0), mn1 = fmaxf(m1, rmax1);
        float fact0 = __expf(m0 - mn0), fact1 = __expf(m1 - mn1);
        m0 = mn0; m1 = mn1;
        float sum0 = 0.f, sum1 = 0.f;
#pragma unroll
        for (int nt = 0; nt < 8; ++nt) {
            sacc[nt][0] = __expf(sacc[nt][0] - mn0); sum0 += sacc[nt][0];
            sacc[nt][1] = __expf(sacc[nt][1] - mn0); sum0 += sacc[nt][1];
            sacc[nt][2] = __expf(sacc[nt][2] - mn1); sum1 += sacc[nt][2];
            sacc[nt][3] = __expf(sacc[nt][3] - mn1); sum1 += sacc[nt][3];
        }
        sum0 += __shfl_xor_sync(0xffffffffu, sum0, 1);
        sum0 += __shfl_xor_sync(0xffffffffu, sum0, 2);
        sum1 += __shfl_xor_sync(0xffffffffu, sum1, 1);
        sum1 += __shfl_xor_sync(0xffffffffu, sum1, 2);
        l0 = l0 * fact0 + sum0;
        l1 = l1 * fact1 + sum1;
#pragma unroll
        for (int nt = 0; nt < 16; ++nt) {
            oacc[nt][0] *= fact0; oacc[nt][1] *= fact0;
            oacc[nt][2] *= fact1; oacc[nt][3] *= fact1;
        }

        // ---- O += P V (V from vcur), 3-term ----
        const uint32_t aVhc = vcur, aVlc = vcur + 128 * VSTR * 2;
#pragma unroll
        for (int j = 0; j < 4; ++j) {
            uint32_t aPh[4], aPl[4];
#pragma unroll
            for (int hlf = 0; hlf < 2; ++hlf) {
                const float* p = sacc[2 * j + hlf];
                aPh[2 * hlf]     = pack_hi(p[0], p[1]);
                aPh[2 * hlf + 1] = pack_hi(p[2], p[3]);
                aPl[2 * hlf]     = pack_lo(p[0], p[1]);
                aPl[2 * hlf + 1] = pack_lo(p[2], p[3]);
            }
#pragma unroll
            for (int nn = 0; nn < 8; ++nn) {
                uint32_t fVh[4], fVl[4];
                uint32_t voff = (uint32_t)((nn * 16 + (q >> 1) * 8 + rr) * (VSTR * 2)
                                           + (j * 16 + (q & 1) * 8) * 2);
                ldsm4(fVh, aVhc + voff);
                ldsm4(fVl, aVlc + voff);
                mma16816(oacc[2 * nn], aPh, &fVh[0]);
                mma16816(oacc[2 * nn], aPl, &fVh[0]);
                mma16816(oacc[2 * nn], aPh, &fVl[0]);
                mma16816(oacc[2 * nn + 1], aPh, &fVh[2]);
                mma16816(oacc[2 * nn + 1], aPl, &fVh[2]);
                mma16816(oacc[2 * nn + 1], aPh, &fVl[2]);
            }
        }
    }

    // ---- normalize + store O as bf16 hi/lo ----
    float inv0 = 1.0f / l0, inv1 = 1.0f / l1;
    const int row0g = b * L_ + qt * 64 + wid * 16 + gr;
    __nv_bfloat16* oh0 = Oh + (size_t)row0g * HID_ + head * HDIM_;
    __nv_bfloat16* ol0 = Ol + (size_t)row0g * HID_ + head * HDIM_;
    __nv_bfloat16* oh1 = oh0 + (size_t)8 * HID_;
    __nv_bfloat16* ol1 = ol0 + (size_t)8 * HID_;
#pragma unroll
    for (int nt = 0; nt < 16; ++nt) {
        int col = nt * 8 + tg * 2;
        float v0 = oacc[nt][0] * inv0, v1 = oacc[nt][1] * inv0;
        float v2 = oacc[nt][2] * inv1, v3 = oacc[nt][3] * inv1;
        *(uint32_t*)(oh0 + col) = pack_hi(v0, v1);
        *(uint32_t*)(ol0 + col) = pack_lo(v0, v1);
        *(uint32_t*)(oh1 + col) = pack_hi(v2, v3);
        *(uint32_t*)(ol1 + col) = pack_lo(v2, v3);
    }
}

// ---------------------------------------------------------------------------
extern "C" void kernel_launch(void* const* d_in, const int* in_sizes, int n_in,
                              void* d_out, int out_size)
{
    const float* query = (const float*)d_in[0];
    const float* kv    = (const float*)d_in[1];
    const float* Wq    = (const float*)d_in[2];
    const float* bq    = (const float*)d_in[3];
    const float* Wkv   = (const float*)d_in[4];
    const float* bkv   = (const float*)d_in[5];
    const float* Wo    = (const float*)d_in[6];
    const float* bo    = (const float*)d_in[7];
    float* out = (float*)d_out;

    float* pv = nullptr;
    cudaGetSymbolAddress((void**)&pv, g_v);
    __nv_bfloat16 *qh, *ql, *kvh, *kvl, *ath, *atl;
    __nv_bfloat16 *wqh, *wql, *wkh, *wkl, *woh, *wol;
    __nv_bfloat16 *aqh, *aql, *akh, *akl, *avh, *avl;
    cudaGetSymbolAddress((void**)&qh,  g_qin_h);  cudaGetSymbolAddress((void**)&ql,  g_qin_l);
    cudaGetSymbolAddress((void**)&kvh, g_kvin_h); cudaGetSymbolAddress((void**)&kvl, g_kvin_l);
    cudaGetSymbolAddress((void**)&ath, g_att_h);  cudaGetSymbolAddress((void**)&atl, g_att_l);
    cudaGetSymbolAddress((void**)&wqh, g_wqt_h);  cudaGetSymbolAddress((void**)&wql, g_wqt_l);
    cudaGetSymbolAddress((void**)&wkh, g_wkvt_h); cudaGetSymbolAddress((void**)&wkl, g_wkvt_l);
    cudaGetSymbolAddress((void**)&woh, g_wot_h);  cudaGetSymbolAddress((void**)&wol, g_wot_l);
    cudaGetSymbolAddress((void**)&aqh, g_aqh);    cudaGetSymbolAddress((void**)&aql, g_aql);
    cudaGetSymbolAddress((void**)&akh, g_kh);     cudaGetSymbolAddress((void**)&akl, g_kl);
    cudaGetSymbolAddress((void**)&avh, g_vth);    cudaGetSymbolAddress((void**)&avl, g_vtl);

    cudaFuncSetAttribute(attn_tc_k, cudaFuncAttributeMaxDynamicSharedMemorySize,
                         ATT_SMEM);
    cudaFuncSetAttribute(hgemm_db_k, cudaFuncAttributeMaxDynamicSharedMemorySize,
                         GEMM_DSMEM);

    const int n_act4 = (MROWS * HID_) / 4;
    const float qscale = 0.08838834764831845f;   // 1/sqrt(128)

    split_k<<<(n_act4 + 255) / 256, 256>>>(query, qh, ql, n_act4, 1.0f);            // 0
    tsplit_k<<<dim3(HID_ / 32, HID_ / 32), dim3(32, 8)>>>(Wq, wqh, wql, HID_, HID_); // 1
    split_k<<<(n_act4 + 255) / 256, 256>>>(kv, kvh, kvl, n_act4, 1.0f);             // 2
    // 3: Q projection (ncu capture slot)
    hgemm_db_k<<<dim3(HID_ / 128, MROWS / 128), 256, GEMM_DSMEM>>>(
        qh, ql, wqh, wql, bq, nullptr, aqh, aql, qscale, MROWS, HID_, HID_, 1);
    tsplit_k<<<dim3(KVW / 32, HID_ / 32), dim3(32, 8)>>>(Wkv, wkh, wkl, HID_, KVW); // 4
    // 5: KV projection -> K [b,kvh,l,d] bf16 hi/lo; V fp32
    hgemm_db_k<<<dim3(KVW / 128, MROWS / 128), 256, GEMM_DSMEM>>>(
        kvh, kvl, wkh, wkl, bkv, pv, akh, akl, 1.0f, MROWS, KVW, HID_, 2);
    tsplit_k<<<dim3(HID_ / 32, HID_ / 32), dim3(32, 8)>>>(Wo, woh, wol, HID_, HID_); // 6
    vtprep_k<<<dim3(L_ / 32, HDIM_ / 32, B_ * NKV_), dim3(32, 8)>>>(pv, avh, avl);   // 7
    // 8: tensor-core attention (double-buffered V, overlapped K refill)
    attn_tc_k<<<dim3(L_ / 64, NHEAD_, B_), 128, ATT_SMEM>>>(
        aqh, aql, akh, akl, avh, avl, ath, atl);
    // 9: O projection -> fp32 out
    hgemm_db_k<<<dim3(HID_ / 128, MROWS / 128), 256, GEMM_DSMEM>>>(
        ath, atl, woh, wol, bo, out, nullptr, nullptr, 1.0f, MROWS, HID_, HID_, 0);
}